// round 15
// baseline (speedup 1.0000x reference)
#include <cuda_runtime.h>

// LIF spike recurrence, T=8:
//   mem = mem*TAU + x[t]*alpha; spike = (mem - Vth) > 0; mem = (1-spike)*mem
//
// FINAL — certified champion over 14 measured rounds.
// Champion distribution: {43.49, 43.55, 43.52, 43.52, 44.48} us; harness
// run-to-run noise ~1us (R14 calibration); nearest rival variant 45.2us.
//
// Configuration:
//   * one thread per 4 spatial positions (float4), grid 4096 x 256
//   * all 8 timestep loads front-batched (8 independent LDG.128, __ldcs)
//   * LIF recurrence entirely in registers, branchless selects
//   * 8 batched STG.128 with __stcs (evict-first streaming)
//
// Roofline: 268MB irreducible fp32 r/w traffic; kernel time 35.5-37.6us
// across ALL variants = ~7.3TB/s effective = 91% of the 8TB/s HBM3e floor
// (33.5us). HBM-bound; no remaining lever exceeds the measured noise band.
//
// Falsified axes (all measured): load policy (default/nc.evict_last),
// store policy (default/wt/cache_hint-evict_last), persistent grid, forced
// occupancy, block=128, 256-bit accesses, L2 residency pinning (both
// directions).

#define TAU 0.5f

__global__ void __launch_bounds__(256) lif_spike_kernel(
    const float* __restrict__ x,
    const float* __restrict__ alpha_p,
    const float* __restrict__ vth_p,
    float* __restrict__ out,
    int spatial /* elements per timestep */)
{
    const float alpha = __ldg(alpha_p);
    const float vth   = __ldg(vth_p);

    const int i4 = (blockIdx.x * blockDim.x + threadIdx.x) * 4;
    if (i4 >= spatial) return;

    // ── Front-batch all 8 timestep loads (8 independent LDG.128) ──
    float4 xt[8];
    #pragma unroll
    for (int t = 0; t < 8; t++) {
        xt[t] = __ldcs(reinterpret_cast<const float4*>(
            x + (size_t)t * (size_t)spatial + i4));
    }

    // ── Recurrence in registers ──
    float m0 = 0.f, m1 = 0.f, m2 = 0.f, m3 = 0.f;
    float4 s[8];
    #pragma unroll
    for (int t = 0; t < 8; t++) {
        m0 = m0 * TAU + xt[t].x * alpha;
        m1 = m1 * TAU + xt[t].y * alpha;
        m2 = m2 * TAU + xt[t].z * alpha;
        m3 = m3 * TAU + xt[t].w * alpha;

        s[t].x = (m0 > vth) ? 1.f : 0.f;
        s[t].y = (m1 > vth) ? 1.f : 0.f;
        s[t].z = (m2 > vth) ? 1.f : 0.f;
        s[t].w = (m3 > vth) ? 1.f : 0.f;

        // hard reset on spike
        m0 = (m0 > vth) ? 0.f : m0;
        m1 = (m1 > vth) ? 0.f : m1;
        m2 = (m2 > vth) ? 0.f : m2;
        m3 = (m3 > vth) ? 0.f : m3;
    }

    // ── Batched streaming stores ──
    #pragma unroll
    for (int t = 0; t < 8; t++) {
        __stcs(reinterpret_cast<float4*>(
            out + (size_t)t * (size_t)spatial + i4), s[t]);
    }
}

extern "C" void kernel_launch(void* const* d_in, const int* in_sizes, int n_in,
                              void* d_out, int out_size) {
    const float* x     = (const float*)d_in[0];
    const float* alpha = (const float*)d_in[1];
    const float* vth   = (const float*)d_in[2];
    float* out = (float*)d_out;

    const int total   = in_sizes[0];     // T * spatial
    const int spatial = total / 8;       // T = 8

    const int threads = 256;
    const int elems_per_thread = 4;
    const int blocks = (spatial + threads * elems_per_thread - 1) /
                       (threads * elems_per_thread);

    lif_spike_kernel<<<blocks, threads>>>(x, alpha, vth, out, spatial);
}

// round 16
// speedup vs baseline: 1.0294x; 1.0294x over previous
#include <cuda_runtime.h>

// LIF spike recurrence, T=8:
//   mem = mem*TAU + x[t]*alpha; spike = (mem - Vth) > 0; mem = (1-spike)*mem
//
// FINAL — certified champion over 15 measured rounds.
// Champion (this exact source) benched 6x: {43.49, 43.55, 43.52, 43.52,
// 44.48, 44.77} us; best mean and best min of all 10 structural variants
// tested. Identical-source drift (+-0.7us) now exceeds any remaining
// candidate delta, so further A/B rounds are uninformative.
//
// Configuration:
//   * one thread per 4 spatial positions (float4), grid 4096 x 256
//   * all 8 timestep loads front-batched (8 independent LDG.128, __ldcs)
//   * LIF recurrence entirely in registers, branchless selects
//   * 8 batched STG.128 with __stcs (evict-first streaming)
//
// Roofline: 268MB irreducible fp32 r/w traffic; kernel time 35.5-37.6us
// across ALL variants = ~7.3TB/s effective = 91% of the 8TB/s HBM3e floor
// (33.5us). HBM-bound streaming kernel at its roofline.
//
// Falsified axes (all measured): load policy (default / nc.L2::evict_last
// 256-bit), store policy (default / __stwt / cache_hint evict_last),
// persistent grid, forced 8-CTA/SM occupancy, block=128, 256-bit accesses,
// L2 residency pinning of input (R7) and output (R9).

#define TAU 0.5f

__global__ void __launch_bounds__(256) lif_spike_kernel(
    const float* __restrict__ x,
    const float* __restrict__ alpha_p,
    const float* __restrict__ vth_p,
    float* __restrict__ out,
    int spatial /* elements per timestep */)
{
    const float alpha = __ldg(alpha_p);
    const float vth   = __ldg(vth_p);

    const int i4 = (blockIdx.x * blockDim.x + threadIdx.x) * 4;
    if (i4 >= spatial) return;

    // ── Front-batch all 8 timestep loads (8 independent LDG.128) ──
    float4 xt[8];
    #pragma unroll
    for (int t = 0; t < 8; t++) {
        xt[t] = __ldcs(reinterpret_cast<const float4*>(
            x + (size_t)t * (size_t)spatial + i4));
    }

    // ── Recurrence in registers ──
    float m0 = 0.f, m1 = 0.f, m2 = 0.f, m3 = 0.f;
    float4 s[8];
    #pragma unroll
    for (int t = 0; t < 8; t++) {
        m0 = m0 * TAU + xt[t].x * alpha;
        m1 = m1 * TAU + xt[t].y * alpha;
        m2 = m2 * TAU + xt[t].z * alpha;
        m3 = m3 * TAU + xt[t].w * alpha;

        s[t].x = (m0 > vth) ? 1.f : 0.f;
        s[t].y = (m1 > vth) ? 1.f : 0.f;
        s[t].z = (m2 > vth) ? 1.f : 0.f;
        s[t].w = (m3 > vth) ? 1.f : 0.f;

        // hard reset on spike
        m0 = (m0 > vth) ? 0.f : m0;
        m1 = (m1 > vth) ? 0.f : m1;
        m2 = (m2 > vth) ? 0.f : m2;
        m3 = (m3 > vth) ? 0.f : m3;
    }

    // ── Batched streaming stores ──
    #pragma unroll
    for (int t = 0; t < 8; t++) {
        __stcs(reinterpret_cast<float4*>(
            out + (size_t)t * (size_t)spatial + i4), s[t]);
    }
}

extern "C" void kernel_launch(void* const* d_in, const int* in_sizes, int n_in,
                              void* d_out, int out_size) {
    const float* x     = (const float*)d_in[0];
    const float* alpha = (const float*)d_in[1];
    const float* vth   = (const float*)d_in[2];
    float* out = (float*)d_out;

    const int total   = in_sizes[0];     // T * spatial
    const int spatial = total / 8;       // T = 8

    const int threads = 256;
    const int elems_per_thread = 4;
    const int blocks = (spatial + threads * elems_per_thread - 1) /
                       (threads * elems_per_thread);

    lif_spike_kernel<<<blocks, threads>>>(x, alpha, vth, out, spatial);
}